// round 8
// baseline (speedup 1.0000x reference)
#include <cuda_runtime.h>

#define TOTAL_OPS 102400
#define ND 1024
#define NW 64
#define E 256
#define H1N 32
#define H2N 16

// ---------------- device scratch (no allocations allowed) ----------------
__device__ float    g_yw_op[ND * H1N];
__device__ float    g_yw_pr[ND * H1N];
__device__ unsigned g_maxbits;
__device__ float    g_sum;
__device__ unsigned g_cnt1;
__device__ unsigned g_cnt2;

typedef unsigned long long ull;

// ---------------- packed fp32x2 helpers (sm_103a FFMA2 path) ----------------
__device__ __forceinline__ ull fma2(ull a, ull b, ull c) {
    ull d;
    asm("fma.rn.f32x2 %0, %1, %2, %3;" : "=l"(d) : "l"(a), "l"(b), "l"(c));
    return d;
}
__device__ __forceinline__ ull splat2(float x) {
    ull d;
    asm("mov.b64 %0, {%1, %1};" : "=l"(d) : "f"(x));
    return d;
}
__device__ __forceinline__ void unpack2(ull v, float& lo, float& hi) {
    asm("mov.b64 {%0, %1}, %2;" : "=f"(lo), "=f"(hi) : "l"(v));
}

// monotone float -> unsigned map for atomicMax
__device__ __forceinline__ unsigned encf(float f) {
    unsigned b = __float_as_uint(f);
    return (b & 0x80000000u) ? ~b : (b | 0x80000000u);
}
__device__ __forceinline__ float decf(unsigned u) {
    return (u & 0x80000000u) ? __uint_as_float(u & 0x7FFFFFFFu)
                             : __uint_as_float(~u);
}

// ---------------- K1: per-dag tables yW = y@W1y + (b1 + z@W1z) --------------
__global__ void __launch_bounds__(128) k_pre(
    const float* __restrict__ opW1, const float* __restrict__ opb1,
    const float* __restrict__ prW1, const float* __restrict__ prb1,
    const float* __restrict__ z, const float* __restrict__ y)
{
    __shared__ __align__(16) float sW[E * H1N];
    __shared__ float szc[H1N];
    int b = blockIdx.x;
    int t = threadIdx.x;
    int table = b >> 4;
    int d0 = (b & 15) * 64;
    const float* W1 = table ? prW1 : opW1;
    const float* b1 = table ? prb1 : opb1;
    int f4off = table ? (1 * H1N / 4) : (E * H1N / 4);
    int offZ  = table ? (E + 1) : (2 * E);
    float* outT = table ? g_yw_pr : g_yw_op;

    if (b == 0 && t == 0) { g_maxbits = 0u; g_sum = 0.f; g_cnt1 = 0u; g_cnt2 = 0u; }

    const float4* gW4 = (const float4*)W1;
    float4* sW4 = (float4*)sW;
#pragma unroll
    for (int i = 0; i < 16; i++) sW4[i * 128 + t] = gW4[f4off + i * 128 + t];

    {
        int j = t >> 2, sub = t & 3;
        const float* Wz = W1 + (size_t)(offZ + sub * 64) * H1N + j;
        float c = 0.f;
#pragma unroll 8
        for (int kk = 0; kk < 64; kk++) c += z[sub * 64 + kk] * Wz[kk * H1N];
        c += __shfl_xor_sync(0xffffffffu, c, 1);
        c += __shfl_xor_sync(0xffffffffu, c, 2);
        if (sub == 0) szc[j] = c + b1[j];
    }
    __syncthreads();

    int d = d0 + (t >> 1);
    int half = t & 1;
    ull acc[16];
#pragma unroll
    for (int q = 0; q < 16; q++) acc[q] = 0ull;
    const float4* yr = (const float4*)&y[d * E];
    const ulonglong2* sWu = (const ulonglong2*)sW;

    int kc0 = half * 32;
    float4 va = yr[kc0];
    for (int kc = 0; kc < 32; kc++) {
        float4 pa = yr[kc0 + ((kc + 1) & 31)];
        float f[4] = {va.x, va.y, va.z, va.w};
#pragma unroll
        for (int kk = 0; kk < 4; kk++) {
            ull xd = splat2(f[kk]);
            const ulonglong2* w = &sWu[((kc0 + kc) * 4 + kk) * 8];
#pragma unroll
            for (int q = 0; q < 8; q++) {
                ulonglong2 wv = w[q];
                acc[2 * q]     = fma2(xd, wv.x, acc[2 * q]);
                acc[2 * q + 1] = fma2(xd, wv.y, acc[2 * q + 1]);
            }
        }
        va = pa;
    }
    float h[H1N];
#pragma unroll
    for (int q = 0; q < 16; q++) unpack2(acc[q], h[2 * q], h[2 * q + 1]);
#pragma unroll
    for (int j = 0; j < H1N; j++)
        h[j] += __shfl_xor_sync(0xffffffffu, h[j], 1);
    if (half == 0) {
#pragma unroll
        for (int j = 0; j < H1N; j++) outT[d * H1N + j] = h[j] + szc[j];
    }
}

// ---------------- K2: prlvl branch, 8 dags/block ----------------
__global__ void __launch_bounds__(512) k_prlvl(
    const float* __restrict__ prW1, const float* __restrict__ prW2,
    const float* __restrict__ prb2, const float* __restrict__ prW3,
    const float* __restrict__ prb3, const float* __restrict__ msk,
    float* __restrict__ out, int nops)
{
    __shared__ __align__(16) float sW2[H1N * H2N];
    __shared__ float sb2[H2N], sW3[H2N];
    __shared__ float sb3;
    __shared__ float sw1[H1N];
    __shared__ float sbase[8 * H1N];
    __shared__ float redm[8][2], reds[8][2];

    int t = threadIdx.x;
    int g = t >> 6;
    int w = t & 63;
    int d = blockIdx.x * 8 + g;

    if (t < H1N * H2N) sW2[t] = prW2[t];
    if (t < H2N) { sb2[t] = prb2[t]; sW3[t] = prW3[t]; }
    if (t == 0) sb3 = prb3[0];
    if (t < H1N) sw1[t] = prW1[t];
    if (t < 8 * H1N) sbase[t] = g_yw_pr[blockIdx.x * 8 * H1N + t];
    __syncthreads();

    float limit = (float)(w + 1);
    const float* base = &sbase[g * H1N];
    float h2[H2N];
#pragma unroll
    for (int j2 = 0; j2 < H2N; j2++) h2[j2] = sb2[j2];
#pragma unroll
    for (int j = 0; j < H1N; j++) {
        float v = fmaxf(base[j] + limit * sw1[j], 0.f);
        const float4* w2 = (const float4*)&sW2[j * H2N];
#pragma unroll
        for (int q2 = 0; q2 < 4; q2++) {
            float4 wv = w2[q2];
            h2[4 * q2 + 0] += v * wv.x;
            h2[4 * q2 + 1] += v * wv.y;
            h2[4 * q2 + 2] += v * wv.z;
            h2[4 * q2 + 3] += v * wv.w;
        }
    }
    float logit = sb3;
#pragma unroll
    for (int j2 = 0; j2 < H2N; j2++) logit += fmaxf(h2[j2], 0.f) * sW3[j2];
    logit -= (1.f - msk[d * NW + w]) * 1000.f;

    float m = logit;
#pragma unroll
    for (int o = 16; o > 0; o >>= 1) m = fmaxf(m, __shfl_xor_sync(0xffffffffu, m, o));
    if ((w & 31) == 0) redm[g][w >> 5] = m;
    __syncthreads();
    m = fmaxf(redm[g][0], redm[g][1]);
    float e = expf(logit - m);
    float s = e;
#pragma unroll
    for (int o = 16; o > 0; o >>= 1) s += __shfl_xor_sync(0xffffffffu, s, o);
    if ((w & 31) == 0) reds[g][w >> 5] = s;
    __syncthreads();
    s = reds[g][0] + reds[g][1];
    out[nops + d * NW + w] = e / s;
}

// ---------------- K3: op MLP + fused global softmax -------------------------
// 128 thr/block, 256 rows/block. Warp w owns cols [8w,8w+8); lane l owns rows
// {l+32i}. 8x8 register tile per thread (64 regs), weights via broadcast
// LDS.128 (2/warp/k), x staged to SMEM with register double-buffering.
// Tail: two grid-wide spin barriers (all 400 CTAs resident at 3/SM).
#define XSTRIDE 264
#define XBUF (16 * XSTRIDE)

__global__ void __launch_bounds__(128, 3) k_ops(
    const float* __restrict__ x, const float* __restrict__ opW1,
    const float* __restrict__ opW2, const float* __restrict__ opb2,
    const float* __restrict__ opW3, const float* __restrict__ opb3,
    const float* __restrict__ op_msk, const int* __restrict__ num_ops,
    float* __restrict__ out, int nrows)
{
    extern __shared__ float dynS[];
    float* sW = dynS;                    // 8192 floats: W1 x-part [k][32]
    float* sX = dynS + E * H1N;          // 2 x 16 x 264 floats (reused as h1 stage)

    __shared__ int sCum[ND];
    __shared__ __align__(16) float sW2[H1N * H2N];
    __shared__ float sb2[H2N], sW3[H2N];
    __shared__ float sb3;
    __shared__ float wred[4];
    __shared__ int wsum[4];
    __shared__ float sBcast;

    int t = threadIdx.x;
    int w = t >> 5, l = t & 31;
    int row0 = blockIdx.x * 256;

    // --- stage W1 x-part: same layout as gmem [k][32] ---
    {
        const float4* gW4 = (const float4*)opW1;
        float4* sW4 = (float4*)sW;
#pragma unroll
        for (int i = 0; i < 16; i++) sW4[i * 128 + t] = gW4[i * 128 + t];
    }
    for (int i = t; i < H1N * H2N; i += 128) sW2[i] = opW2[i];
    if (t < H2N) { sb2[t] = opb2[t]; sW3[t] = opW3[t]; }
    if (t == 0) sb3 = opb3[0];

    // --- inline inclusive scan of num_ops into sCum ---
    {
        int vloc[8]; int tsum = 0;
#pragma unroll
        for (int i = 0; i < 8; i++) { vloc[i] = num_ops[t * 8 + i]; tsum += vloc[i]; }
        int sc = tsum;
#pragma unroll
        for (int o = 1; o < 32; o <<= 1) {
            int nv = __shfl_up_sync(0xffffffffu, sc, o);
            if (l >= o) sc += nv;
        }
        if (l == 31) wsum[w] = sc;
        __syncthreads();
        int woff = 0;
#pragma unroll
        for (int q = 0; q < 4; q++) if (q < w) woff += wsum[q];
        int run = woff + sc - tsum;
#pragma unroll
        for (int i = 0; i < 8; i++) { run += vloc[i]; sCum[t * 8 + i] = run; }
    }

    // --- main GEMM: 16 chunks of 16 k, register double-buffered staging ---
    ull acc[8][4];
#pragma unroll
    for (int i = 0; i < 8; i++)
#pragma unroll
        for (int c = 0; c < 4; c++) acc[i][c] = 0ull;

    float4 pf[8];
    // prologue: load + store chunk 0
#pragma unroll
    for (int i = 0; i < 8; i++) {
        int f4 = i * 128 + t, r = f4 >> 2, c4 = f4 & 3;
        int row = min(row0 + r, nrows - 1);
        pf[i] = *(const float4*)&x[(size_t)row * E + 0 * 16 + c4 * 4];
    }
#pragma unroll
    for (int i = 0; i < 8; i++) {
        int f4 = i * 128 + t, r = f4 >> 2, c4 = f4 & 3;
        float* d = &sX[(c4 * 4) * XSTRIDE + r];
        d[0] = pf[i].x; d[XSTRIDE] = pf[i].y;
        d[2 * XSTRIDE] = pf[i].z; d[3 * XSTRIDE] = pf[i].w;
    }

    for (int kc = 0; kc < 16; kc++) {
        if (kc < 15) {
#pragma unroll
            for (int i = 0; i < 8; i++) {
                int f4 = i * 128 + t, r = f4 >> 2, c4 = f4 & 3;
                int row = min(row0 + r, nrows - 1);
                pf[i] = *(const float4*)&x[(size_t)row * E + (kc + 1) * 16 + c4 * 4];
            }
        }
        __syncthreads();                       // chunk kc visible in buf kc&1
        const float* xb = &sX[(kc & 1) * XBUF];
        const float* wb = &sW[kc * 16 * H1N + w * 8];
#pragma unroll
        for (int kk = 0; kk < 16; kk++) {
            float xv[8];
#pragma unroll
            for (int i = 0; i < 8; i++) xv[i] = xb[kk * XSTRIDE + l + 32 * i];
            ulonglong2 w0 = *(const ulonglong2*)&wb[kk * H1N];
            ulonglong2 w1 = *(const ulonglong2*)&wb[kk * H1N + 4];
#pragma unroll
            for (int i = 0; i < 8; i++) {
                ull s = splat2(xv[i]);
                acc[i][0] = fma2(s, w0.x, acc[i][0]);
                acc[i][1] = fma2(s, w0.y, acc[i][1]);
                acc[i][2] = fma2(s, w1.x, acc[i][2]);
                acc[i][3] = fma2(s, w1.y, acc[i][3]);
            }
        }
        if (kc < 15) {
            float* dst = &sX[((kc + 1) & 1) * XBUF];
#pragma unroll
            for (int i = 0; i < 8; i++) {
                int f4 = i * 128 + t, r = f4 >> 2, c4 = f4 & 3;
                float* d = &dst[(c4 * 4) * XSTRIDE + r];
                d[0] = pf[i].x; d[XSTRIDE] = pf[i].y;
                d[2 * XSTRIDE] = pf[i].z; d[3 * XSTRIDE] = pf[i].w;
            }
        }
    }

    // --- stage h1 to SMEM (stride-33, conflict-free), reuse sX region ---
    __syncthreads();
    float* hst = sX;
#pragma unroll
    for (int i = 0; i < 8; i++) {
        int row = l + 32 * i;
        float* d = &hst[row * 33 + w * 8];
#pragma unroll
        for (int cp = 0; cp < 4; cp++)
            unpack2(acc[i][cp], d[2 * cp], d[2 * cp + 1]);
    }
    __syncthreads();

    // --- epilogue: 2 rows per thread, logits stay in registers ---
    float lg[2];
    float m = -3.402823466e38f;
#pragma unroll
    for (int r = 0; r < 2; r++) {
        int lr = t + r * 128;
        int i = row0 + lr;
        lg[r] = -3.402823466e38f;
        if (i < nrows) {
            int d = 0;
#pragma unroll
            for (int s = 512; s > 0; s >>= 1)
                if (d + s <= ND - 1 && sCum[d + s - 1] <= i) d += s;
            const float* hs = &hst[lr * 33];
            const float* bw = &g_yw_op[d * H1N];
            float h2[H2N];
#pragma unroll
            for (int j2 = 0; j2 < H2N; j2++) h2[j2] = sb2[j2];
#pragma unroll
            for (int j = 0; j < H1N; j++) {
                float v = fmaxf(hs[j] + bw[j], 0.f);
                const float4* w2 = (const float4*)&sW2[j * H2N];
#pragma unroll
                for (int q2 = 0; q2 < 4; q2++) {
                    float4 wv = w2[q2];
                    h2[4 * q2 + 0] += v * wv.x;
                    h2[4 * q2 + 1] += v * wv.y;
                    h2[4 * q2 + 2] += v * wv.z;
                    h2[4 * q2 + 3] += v * wv.w;
                }
            }
            float logit = sb3;
#pragma unroll
            for (int j2 = 0; j2 < H2N; j2++) logit += fmaxf(h2[j2], 0.f) * sW3[j2];
            logit -= (1.f - op_msk[i]) * 1000.f;
            lg[r] = logit;
            m = fmaxf(m, logit);
        }
    }

    // --- block max -> global atomicMax ---
#pragma unroll
    for (int o = 16; o > 0; o >>= 1) m = fmaxf(m, __shfl_xor_sync(0xffffffffu, m, o));
    if (l == 0) wred[w] = m;
    __syncthreads();

    // --- grid barrier 1: all logits' maxes published ---
    if (t == 0) {
        float bm = fmaxf(fmaxf(wred[0], wred[1]), fmaxf(wred[2], wred[3]));
        atomicMax(&g_maxbits, encf(bm));
        __threadfence();
        atomicAdd(&g_cnt1, 1u);
        volatile unsigned* vc = &g_cnt1;
        while (*vc < gridDim.x) { }
        __threadfence();
        sBcast = decf(*(volatile unsigned*)&g_maxbits);
    }
    __syncthreads();
    float gm = sBcast;

    // --- exp + block sum -> global atomicAdd ---
    float e0 = (lg[0] > -1e38f) ? expf(lg[0] - gm) : 0.f;
    float e1 = (lg[1] > -1e38f) ? expf(lg[1] - gm) : 0.f;
    float s = e0 + e1;
#pragma unroll
    for (int o = 16; o > 0; o >>= 1) s += __shfl_xor_sync(0xffffffffu, s, o);
    if (l == 0) wred[w] = s;
    __syncthreads();

    // --- grid barrier 2: global sum complete ---
    if (t == 0) {
        float bs = wred[0] + wred[1] + wred[2] + wred[3];
        atomicAdd(&g_sum, bs);
        __threadfence();
        atomicAdd(&g_cnt2, 1u);
        volatile unsigned* vc = &g_cnt2;
        while (*vc < gridDim.x) { }
        __threadfence();
        sBcast = 1.f / *(volatile float*)&g_sum;
    }
    __syncthreads();
    float inv = sBcast;

    int i0 = row0 + t, i1 = row0 + t + 128;
    if (i0 < nrows) out[i0] = e0 * inv;
    if (i1 < nrows) out[i1] = e1 * inv;
}

// ---------------- launcher ----------------
extern "C" void kernel_launch(void* const* d_in, const int* in_sizes, int n_in,
                              void* d_out, int out_size) {
    int o = (n_in >= 20) ? 2 : 0;
    const int*   num_ops = (const int*)d_in[0];
    const float* x       = (const float*)d_in[1 + o];
    const float* y       = (const float*)d_in[2 + o];
    const float* z       = (const float*)d_in[3 + o];
    const float* op_msk  = (const float*)d_in[4 + o];
    const float* pr_msk  = (const float*)d_in[5 + o];
    const float* opW1    = (const float*)d_in[6 + o];
    const float* opb1    = (const float*)d_in[7 + o];
    const float* opW2    = (const float*)d_in[8 + o];
    const float* opb2    = (const float*)d_in[9 + o];
    const float* opW3    = (const float*)d_in[10 + o];
    const float* opb3    = (const float*)d_in[11 + o];
    const float* prW1    = (const float*)d_in[12 + o];
    const float* prb1    = (const float*)d_in[13 + o];
    const float* prW2    = (const float*)d_in[14 + o];
    const float* prb2    = (const float*)d_in[15 + o];
    const float* prW3    = (const float*)d_in[16 + o];
    const float* prb3    = (const float*)d_in[17 + o];
    float* out = (float*)d_out;

    int n = in_sizes[1 + o] / E;   // total ops (102400)

    static int smem_set = 0;
    int dyn = (E * H1N + 2 * XBUF) * (int)sizeof(float);   // 66560 B
    if (!smem_set) {
        cudaFuncSetAttribute(k_ops, cudaFuncAttributeMaxDynamicSharedMemorySize, dyn);
        smem_set = 1;
    }

    k_pre<<<32, 128>>>(opW1, opb1, prW1, prb1, z, y);
    k_prlvl<<<ND / 8, 512>>>(prW1, prW2, prb2, prW3, prb3, pr_msk, out, n);
    k_ops<<<(n + 255) / 256, 128, dyn>>>(x, opW1, opW2, opb2, opW3, opb3,
                                         op_msk, num_ops, out, n);
}

// round 10
// speedup vs baseline: 1.5139x; 1.5139x over previous
#include <cuda_runtime.h>

#define TOTAL_OPS 102400
#define ND 1024
#define NW 64
#define E 256
#define H1N 32
#define H2N 16

// ---------------- device scratch (no allocations allowed) ----------------
__device__ float    g_yw_op[ND * H1N];   // y@W1y only (zc added by consumer)
__device__ float    g_yw_pr[ND * H1N];
__device__ float    g_zc_op[H1N];        // b1 + z@W1z
__device__ float    g_zc_pr[H1N];
__device__ unsigned g_maxbits;
__device__ float    g_sum;
__device__ unsigned g_cnt1;
__device__ unsigned g_cnt2;

typedef unsigned long long ull;

// ---------------- packed fp32x2 helpers (sm_103a FFMA2 path) ----------------
__device__ __forceinline__ ull fma2(ull a, ull b, ull c) {
    ull d;
    asm("fma.rn.f32x2 %0, %1, %2, %3;" : "=l"(d) : "l"(a), "l"(b), "l"(c));
    return d;
}
__device__ __forceinline__ ull splat2(float x) {
    ull d;
    asm("mov.b64 %0, {%1, %1};" : "=l"(d) : "f"(x));
    return d;
}
__device__ __forceinline__ void unpack2(ull v, float& lo, float& hi) {
    asm("mov.b64 {%0, %1}, %2;" : "=f"(lo), "=f"(hi) : "l"(v));
}

// monotone float -> unsigned map for atomicMax
__device__ __forceinline__ unsigned encf(float f) {
    unsigned b = __float_as_uint(f);
    return (b & 0x80000000u) ? ~b : (b | 0x80000000u);
}
__device__ __forceinline__ float decf(unsigned u) {
    return (u & 0x80000000u) ? __uint_as_float(u & 0x7FFFFFFFu)
                             : __uint_as_float(~u);
}

// ---------------- K1: yW tables, one block per (dag, table) -----------------
// grid = 2050: blocks [0,1024) op dags, [1024,2048) pr dags, 2048/2049 zc.
// Block: 128 thr = 32 cols x 4 k-quarters; coalesced W reads, smem combine.
__global__ void __launch_bounds__(128) k_pre(
    const float* __restrict__ opW1, const float* __restrict__ opb1,
    const float* __restrict__ prW1, const float* __restrict__ prb1,
    const float* __restrict__ z, const float* __restrict__ y)
{
    __shared__ float part[4][H1N];
    int b = blockIdx.x, t = threadIdx.x;
    int j = t & 31, q = t >> 5;

    if (b < 2048) {
        int table = b >> 10, d = b & 1023;
        const float* W1 = table ? prW1 : opW1;
        int offY = table ? 1 : E;
        const float* sp = &y[d * E + q * 64];
        const float* Wp = W1 + (size_t)(offY + q * 64) * H1N + j;
        float c = 0.f;
#pragma unroll 16
        for (int kk = 0; kk < 64; kk++) c += sp[kk] * Wp[kk * H1N];
        part[q][j] = c;
        __syncthreads();
        if (q == 0) {
            float v = part[0][j] + part[1][j] + part[2][j] + part[3][j];
            (table ? g_yw_pr : g_yw_op)[d * H1N + j] = v;
        }
    } else {
        int table = b - 2048;
        const float* W1 = table ? prW1 : opW1;
        const float* b1 = table ? prb1 : opb1;
        int offZ = table ? (E + 1) : (2 * E);
        const float* sp = z + q * 64;
        const float* Wp = W1 + (size_t)(offZ + q * 64) * H1N + j;
        float c = 0.f;
#pragma unroll 16
        for (int kk = 0; kk < 64; kk++) c += sp[kk] * Wp[kk * H1N];
        part[q][j] = c;
        __syncthreads();
        if (q == 0) {
            float v = part[0][j] + part[1][j] + part[2][j] + part[3][j] + b1[j];
            (table ? g_zc_pr : g_zc_op)[j] = v;
        }
        if (table == 0 && t == 0) {
            g_maxbits = 0u; g_sum = 0.f; g_cnt1 = 0u; g_cnt2 = 0u;
        }
    }
}

// ---------------- K2: prlvl branch, 8 dags/block ----------------
__global__ void __launch_bounds__(512) k_prlvl(
    const float* __restrict__ prW1, const float* __restrict__ prW2,
    const float* __restrict__ prb2, const float* __restrict__ prW3,
    const float* __restrict__ prb3, const float* __restrict__ msk,
    float* __restrict__ out, int nops)
{
    __shared__ __align__(16) float sW2[H1N * H2N];
    __shared__ float sb2[H2N], sW3[H2N];
    __shared__ float sb3;
    __shared__ float sw1[H1N], szc[H1N];
    __shared__ float sbase[8 * H1N];
    __shared__ float redm[8][2], reds[8][2];

    int t = threadIdx.x;
    int g = t >> 6;
    int w = t & 63;
    int d = blockIdx.x * 8 + g;

    if (t < H1N * H2N) sW2[t] = prW2[t];
    if (t < H2N) { sb2[t] = prb2[t]; sW3[t] = prW3[t]; }
    if (t == 0) sb3 = prb3[0];
    if (t < H1N) { sw1[t] = prW1[t]; szc[t] = g_zc_pr[t]; }
    if (t < 8 * H1N) sbase[t] = g_yw_pr[blockIdx.x * 8 * H1N + t];
    __syncthreads();

    float limit = (float)(w + 1);
    const float* base = &sbase[g * H1N];
    float h2[H2N];
#pragma unroll
    for (int j2 = 0; j2 < H2N; j2++) h2[j2] = sb2[j2];
#pragma unroll
    for (int j = 0; j < H1N; j++) {
        float v = fmaxf(base[j] + szc[j] + limit * sw1[j], 0.f);
        const float4* w2 = (const float4*)&sW2[j * H2N];
#pragma unroll
        for (int q2 = 0; q2 < 4; q2++) {
            float4 wv = w2[q2];
            h2[4 * q2 + 0] += v * wv.x;
            h2[4 * q2 + 1] += v * wv.y;
            h2[4 * q2 + 2] += v * wv.z;
            h2[4 * q2 + 3] += v * wv.w;
        }
    }
    float logit = sb3;
#pragma unroll
    for (int j2 = 0; j2 < H2N; j2++) logit += fmaxf(h2[j2], 0.f) * sW3[j2];
    logit -= (1.f - msk[d * NW + w]) * 1000.f;

    float m = logit;
#pragma unroll
    for (int o = 16; o > 0; o >>= 1) m = fmaxf(m, __shfl_xor_sync(0xffffffffu, m, o));
    if ((w & 31) == 0) redm[g][w >> 5] = m;
    __syncthreads();
    m = fmaxf(redm[g][0], redm[g][1]);
    float e = expf(logit - m);
    float s = e;
#pragma unroll
    for (int o = 16; o > 0; o >>= 1) s += __shfl_xor_sync(0xffffffffu, s, o);
    if ((w & 31) == 0) reds[g][w >> 5] = s;
    __syncthreads();
    s = reds[g][0] + reds[g][1];
    out[nops + d * NW + w] = e / s;
}

// ---------------- K3: op MLP + fused global softmax -------------------------
// 128 thr, 256 rows/block. Col-split: warps 0-1 cols 0-15, warps 2-3 cols
// 16-31; thread owns 4 rows x 16 cols (32 ull acc). Weights via broadcast
// LDS.128 (4/warp/k); x direct from gmem, register prefetch. Tail: two
// grid-wide spin barriers (>=3 CTA/SM at 40KB smem => 444 resident >= 400).
__global__ void __launch_bounds__(128, 3) k_ops(
    const float* __restrict__ x, const float* __restrict__ opW1,
    const float* __restrict__ opW2, const float* __restrict__ opb2,
    const float* __restrict__ opW3, const float* __restrict__ opb3,
    const float* __restrict__ op_msk, const int* __restrict__ num_ops,
    float* __restrict__ out, int nrows)
{
    __shared__ __align__(16) float sBuf[256 * 33];  // weights (8192) / h1 stage
    __shared__ int sCum[ND];
    __shared__ __align__(16) float sW2[H1N * H2N];
    __shared__ float sb2[H2N], sW3[H2N], szc[H1N];
    __shared__ float sb3;
    __shared__ float wred[4];
    __shared__ int wsum[4];
    __shared__ float sBcast;

    int t = threadIdx.x;
    int w = t >> 5, l = t & 31;
    int row0 = blockIdx.x * 256;

    // --- stage W1 x-part [k][32] + small weights ---
    {
        const float4* gW4 = (const float4*)opW1;
        float4* sW4 = (float4*)sBuf;
#pragma unroll
        for (int i = 0; i < 16; i++) sW4[i * 128 + t] = gW4[i * 128 + t];
    }
    for (int i = t; i < H1N * H2N; i += 128) sW2[i] = opW2[i];
    if (t < H2N) { sb2[t] = opb2[t]; sW3[t] = opW3[t]; }
    if (t < H1N) szc[t] = g_zc_op[t];
    if (t == 0) sb3 = opb3[0];

    // --- inline inclusive scan of num_ops into sCum ---
    {
        int vloc[8]; int tsum = 0;
#pragma unroll
        for (int i = 0; i < 8; i++) { vloc[i] = num_ops[t * 8 + i]; tsum += vloc[i]; }
        int sc = tsum;
#pragma unroll
        for (int o = 1; o < 32; o <<= 1) {
            int nv = __shfl_up_sync(0xffffffffu, sc, o);
            if (l >= o) sc += nv;
        }
        if (l == 31) wsum[w] = sc;
        __syncthreads();
        int woff = 0;
#pragma unroll
        for (int q = 0; q < 4; q++) if (q < w) woff += wsum[q];
        int run = woff + sc - tsum;
#pragma unroll
        for (int i = 0; i < 8; i++) { run += vloc[i]; sCum[t * 8 + i] = run; }
    }
    __syncthreads();

    // --- main GEMM: 4 rows x 16 cols per thread ---
    int colhalf = t >> 6;               // 0: cols 0-15, 1: cols 16-31
    int rt = t & 63;
    const float4* x0 = (const float4*)&x[(size_t)min(row0 + rt,       nrows - 1) * E];
    const float4* x1 = (const float4*)&x[(size_t)min(row0 + rt + 64,  nrows - 1) * E];
    const float4* x2 = (const float4*)&x[(size_t)min(row0 + rt + 128, nrows - 1) * E];
    const float4* x3 = (const float4*)&x[(size_t)min(row0 + rt + 192, nrows - 1) * E];

    ull a0[8], a1[8], a2[8], a3[8];
#pragma unroll
    for (int q = 0; q < 8; q++) { a0[q] = 0ull; a1[q] = 0ull; a2[q] = 0ull; a3[q] = 0ull; }
    const ulonglong2* sWu = (const ulonglong2*)sBuf;

    float4 v0 = x0[0], v1 = x1[0], v2 = x2[0], v3 = x3[0];
    for (int kc = 0; kc < 64; kc++) {
        int kn = (kc + 1) & 63;
        float4 p0 = x0[kn], p1 = x1[kn], p2 = x2[kn], p3 = x3[kn];
        float f0[4] = {v0.x, v0.y, v0.z, v0.w};
        float f1[4] = {v1.x, v1.y, v1.z, v1.w};
        float f2[4] = {v2.x, v2.y, v2.z, v2.w};
        float f3[4] = {v3.x, v3.y, v3.z, v3.w};
#pragma unroll
        for (int kk = 0; kk < 4; kk++) {
            ull s0 = splat2(f0[kk]);
            ull s1 = splat2(f1[kk]);
            ull s2 = splat2(f2[kk]);
            ull s3 = splat2(f3[kk]);
            const ulonglong2* wp = &sWu[(kc * 4 + kk) * 8 + colhalf * 4];
            ulonglong2 w0 = wp[0], w1 = wp[1], w2 = wp[2], w3 = wp[3];
            a0[0] = fma2(s0, w0.x, a0[0]); a0[1] = fma2(s0, w0.y, a0[1]);
            a0[2] = fma2(s0, w1.x, a0[2]); a0[3] = fma2(s0, w1.y, a0[3]);
            a0[4] = fma2(s0, w2.x, a0[4]); a0[5] = fma2(s0, w2.y, a0[5]);
            a0[6] = fma2(s0, w3.x, a0[6]); a0[7] = fma2(s0, w3.y, a0[7]);
            a1[0] = fma2(s1, w0.x, a1[0]); a1[1] = fma2(s1, w0.y, a1[1]);
            a1[2] = fma2(s1, w1.x, a1[2]); a1[3] = fma2(s1, w1.y, a1[3]);
            a1[4] = fma2(s1, w2.x, a1[4]); a1[5] = fma2(s1, w2.y, a1[5]);
            a1[6] = fma2(s1, w3.x, a1[6]); a1[7] = fma2(s1, w3.y, a1[7]);
            a2[0] = fma2(s2, w0.x, a2[0]); a2[1] = fma2(s2, w0.y, a2[1]);
            a2[2] = fma2(s2, w1.x, a2[2]); a2[3] = fma2(s2, w1.y, a2[3]);
            a2[4] = fma2(s2, w2.x, a2[4]); a2[5] = fma2(s2, w2.y, a2[5]);
            a2[6] = fma2(s2, w3.x, a2[6]); a2[7] = fma2(s2, w3.y, a2[7]);
            a3[0] = fma2(s3, w0.x, a3[0]); a3[1] = fma2(s3, w0.y, a3[1]);
            a3[2] = fma2(s3, w1.x, a3[2]); a3[3] = fma2(s3, w1.y, a3[3]);
            a3[4] = fma2(s3, w2.x, a3[4]); a3[5] = fma2(s3, w2.y, a3[5]);
            a3[6] = fma2(s3, w3.x, a3[6]); a3[7] = fma2(s3, w3.y, a3[7]);
        }
        v0 = p0; v1 = p1; v2 = p2; v3 = p3;
    }

    // --- stage h1 to sBuf (stride-33), reuse weight region ---
    __syncthreads();
    {
        float* d0 = &sBuf[(rt      ) * 33 + colhalf * 16];
        float* d1 = &sBuf[(rt +  64) * 33 + colhalf * 16];
        float* d2 = &sBuf[(rt + 128) * 33 + colhalf * 16];
        float* d3 = &sBuf[(rt + 192) * 33 + colhalf * 16];
#pragma unroll
        for (int q = 0; q < 8; q++) {
            unpack2(a0[q], d0[2 * q], d0[2 * q + 1]);
            unpack2(a1[q], d1[2 * q], d1[2 * q + 1]);
            unpack2(a2[q], d2[2 * q], d2[2 * q + 1]);
            unpack2(a3[q], d3[2 * q], d3[2 * q + 1]);
        }
    }
    __syncthreads();

    // --- epilogue: 2 rows per thread, logits stay in registers ---
    float lg[2];
    float m = -3.402823466e38f;
#pragma unroll
    for (int r = 0; r < 2; r++) {
        int lr = t + r * 128;
        int i = row0 + lr;
        lg[r] = -3.402823466e38f;
        if (i < nrows) {
            int d = 0;
#pragma unroll
            for (int s = 512; s > 0; s >>= 1)
                if (d + s <= ND - 1 && sCum[d + s - 1] <= i) d += s;
            const float* hs = &sBuf[lr * 33];
            const float* bw = &g_yw_op[d * H1N];
            float h2[H2N];
#pragma unroll
            for (int j2 = 0; j2 < H2N; j2++) h2[j2] = sb2[j2];
#pragma unroll
            for (int j = 0; j < H1N; j++) {
                float v = fmaxf(hs[j] + bw[j] + szc[j], 0.f);
                const float4* w2 = (const float4*)&sW2[j * H2N];
#pragma unroll
                for (int q2 = 0; q2 < 4; q2++) {
                    float4 wv = w2[q2];
                    h2[4 * q2 + 0] += v * wv.x;
                    h2[4 * q2 + 1] += v * wv.y;
                    h2[4 * q2 + 2] += v * wv.z;
                    h2[4 * q2 + 3] += v * wv.w;
                }
            }
            float logit = sb3;
#pragma unroll
            for (int j2 = 0; j2 < H2N; j2++) logit += fmaxf(h2[j2], 0.f) * sW3[j2];
            logit -= (1.f - op_msk[i]) * 1000.f;
            lg[r] = logit;
            m = fmaxf(m, logit);
        }
    }

#pragma unroll
    for (int o = 16; o > 0; o >>= 1) m = fmaxf(m, __shfl_xor_sync(0xffffffffu, m, o));
    if (l == 0) wred[w] = m;
    __syncthreads();

    // --- grid barrier 1: global max ---
    if (t == 0) {
        float bm = fmaxf(fmaxf(wred[0], wred[1]), fmaxf(wred[2], wred[3]));
        atomicMax(&g_maxbits, encf(bm));
        __threadfence();
        atomicAdd(&g_cnt1, 1u);
        volatile unsigned* vc = &g_cnt1;
        while (*vc < gridDim.x) { }
        __threadfence();
        sBcast = decf(*(volatile unsigned*)&g_maxbits);
    }
    __syncthreads();
    float gm = sBcast;

    float e0 = (lg[0] > -1e38f) ? expf(lg[0] - gm) : 0.f;
    float e1 = (lg[1] > -1e38f) ? expf(lg[1] - gm) : 0.f;
    float s = e0 + e1;
#pragma unroll
    for (int o = 16; o > 0; o >>= 1) s += __shfl_xor_sync(0xffffffffu, s, o);
    if (l == 0) wred[w] = s;
    __syncthreads();

    // --- grid barrier 2: global sum ---
    if (t == 0) {
        float bs = wred[0] + wred[1] + wred[2] + wred[3];
        atomicAdd(&g_sum, bs);
        __threadfence();
        atomicAdd(&g_cnt2, 1u);
        volatile unsigned* vc = &g_cnt2;
        while (*vc < gridDim.x) { }
        __threadfence();
        sBcast = 1.f / *(volatile float*)&g_sum;
    }
    __syncthreads();
    float inv = sBcast;

    int i0 = row0 + t, i1 = row0 + t + 128;
    if (i0 < nrows) out[i0] = e0 * inv;
    if (i1 < nrows) out[i1] = e1 * inv;
}

// ---------------- launcher ----------------
extern "C" void kernel_launch(void* const* d_in, const int* in_sizes, int n_in,
                              void* d_out, int out_size) {
    int o = (n_in >= 20) ? 2 : 0;
    const int*   num_ops = (const int*)d_in[0];
    const float* x       = (const float*)d_in[1 + o];
    const float* y       = (const float*)d_in[2 + o];
    const float* z       = (const float*)d_in[3 + o];
    const float* op_msk  = (const float*)d_in[4 + o];
    const float* pr_msk  = (const float*)d_in[5 + o];
    const float* opW1    = (const float*)d_in[6 + o];
    const float* opb1    = (const float*)d_in[7 + o];
    const float* opW2    = (const float*)d_in[8 + o];
    const float* opb2    = (const float*)d_in[9 + o];
    const float* opW3    = (const float*)d_in[10 + o];
    const float* opb3    = (const float*)d_in[11 + o];
    const float* prW1    = (const float*)d_in[12 + o];
    const float* prb1    = (const float*)d_in[13 + o];
    const float* prW2    = (const float*)d_in[14 + o];
    const float* prb2    = (const float*)d_in[15 + o];
    const float* prW3    = (const float*)d_in[16 + o];
    const float* prb3    = (const float*)d_in[17 + o];
    float* out = (float*)d_out;

    int n = in_sizes[1 + o] / E;   // total ops (102400)

    k_pre<<<2050, 128>>>(opW1, opb1, prW1, prb1, z, y);
    k_prlvl<<<ND / 8, 512>>>(prW1, prW2, prb2, prW3, prb3, pr_msk, out, n);
    k_ops<<<(n + 255) / 256, 128>>>(x, opW1, opW2, opb2, opW3, opb3,
                                    op_msk, num_ops, out, n);
}

// round 11
// speedup vs baseline: 1.7340x; 1.1454x over previous
#include <cuda_runtime.h>

#define TOTAL_OPS 102400
#define ND 1024
#define NW 64
#define E 256
#define H1N 32
#define H2N 16
#define XPAD 20                      // floats per row in x staging buffer

// ---------------- device scratch (no allocations allowed) ----------------
__device__ float    g_yw_op[ND * H1N];   // y@W1y only (zc added by consumer)
__device__ float    g_yw_pr[ND * H1N];
__device__ float    g_zc_op[H1N];        // b1 + z@W1z
__device__ float    g_zc_pr[H1N];
__device__ unsigned g_maxbits;
__device__ float    g_sum;
__device__ unsigned g_cnt1;
__device__ unsigned g_cnt2;

typedef unsigned long long ull;

// ---------------- packed fp32x2 helpers (sm_103a FFMA2 path) ----------------
__device__ __forceinline__ ull fma2(ull a, ull b, ull c) {
    ull d;
    asm("fma.rn.f32x2 %0, %1, %2, %3;" : "=l"(d) : "l"(a), "l"(b), "l"(c));
    return d;
}
__device__ __forceinline__ ull splat2(float x) {
    ull d;
    asm("mov.b64 %0, {%1, %1};" : "=l"(d) : "f"(x));
    return d;
}
__device__ __forceinline__ void unpack2(ull v, float& lo, float& hi) {
    asm("mov.b64 {%0, %1}, %2;" : "=f"(lo), "=f"(hi) : "l"(v));
}

__device__ __forceinline__ unsigned encf(float f) {
    unsigned b = __float_as_uint(f);
    return (b & 0x80000000u) ? ~b : (b | 0x80000000u);
}
__device__ __forceinline__ float decf(unsigned u) {
    return (u & 0x80000000u) ? __uint_as_float(u & 0x7FFFFFFFu)
                             : __uint_as_float(~u);
}

// ---------------- K1: yW tables, 16 dags/block, W cached in SMEM ------------
// grid = 130: blocks [0,64) op dags, [64,128) pr dags, 128/129 zc + resets.
__global__ void __launch_bounds__(128) k_pre(
    const float* __restrict__ opW1, const float* __restrict__ opb1,
    const float* __restrict__ prW1, const float* __restrict__ prb1,
    const float* __restrict__ z, const float* __restrict__ y)
{
    __shared__ __align__(16) float sW[E * H1N];   // 32 KB y-part of W1
    __shared__ float part[2][4][H1N];
    int b = blockIdx.x, t = threadIdx.x;
    int j = t & 31, q = t >> 5;

    if (b < 128) {
        int table = b >> 6, d0 = (b & 63) * 16;
        const float* W1 = table ? prW1 : opW1;
        int f4off = table ? (1 * H1N / 4) : (E * H1N / 4);   // float4 offset
        float* outT = table ? g_yw_pr : g_yw_op;

        const float4* gW4 = (const float4*)W1;
        float4* sW4 = (float4*)sW;
#pragma unroll
        for (int i = 0; i < 16; i++) sW4[i * 128 + t] = gW4[f4off + i * 128 + t];
        __syncthreads();

        const float* sWq = &sW[q * 64 * H1N + j];   // this warp's k-quarter
        for (int dd = 0; dd < 8; dd++) {
            int da = d0 + 2 * dd, db = da + 1;
            const float* ya = &y[(size_t)da * E + q * 64];
            const float* yb = &y[(size_t)db * E + q * 64];
            float ca = 0.f, cb = 0.f;
#pragma unroll 16
            for (int kk = 0; kk < 64; kk++) {
                float wv = sWq[kk * H1N];
                ca += ya[kk] * wv;
                cb += yb[kk] * wv;
            }
            part[0][q][j] = ca;
            part[1][q][j] = cb;
            __syncthreads();
            if (q == 0) {
                outT[da * H1N + j] = part[0][0][j] + part[0][1][j] + part[0][2][j] + part[0][3][j];
                outT[db * H1N + j] = part[1][0][j] + part[1][1][j] + part[1][2][j] + part[1][3][j];
            }
            __syncthreads();
        }
    } else {
        int table = b - 128;
        const float* W1 = table ? prW1 : opW1;
        const float* b1 = table ? prb1 : opb1;
        int offZ = table ? (E + 1) : (2 * E);
        const float* sp = z + q * 64;
        const float* Wp = W1 + (size_t)(offZ + q * 64) * H1N + j;
        float c = 0.f;
#pragma unroll 16
        for (int kk = 0; kk < 64; kk++) c += sp[kk] * Wp[kk * H1N];
        part[0][q][j] = c;
        __syncthreads();
        if (q == 0) {
            float v = part[0][0][j] + part[0][1][j] + part[0][2][j] + part[0][3][j] + b1[j];
            (table ? g_zc_pr : g_zc_op)[j] = v;
        }
        if (table == 0 && t == 0) {
            g_maxbits = 0u; g_sum = 0.f; g_cnt1 = 0u; g_cnt2 = 0u;
        }
    }
}

// ---------------- K2: prlvl branch, 8 dags/block ----------------
__global__ void __launch_bounds__(512) k_prlvl(
    const float* __restrict__ prW1, const float* __restrict__ prW2,
    const float* __restrict__ prb2, const float* __restrict__ prW3,
    const float* __restrict__ prb3, const float* __restrict__ msk,
    float* __restrict__ out, int nops)
{
    __shared__ __align__(16) float sW2[H1N * H2N];
    __shared__ float sb2[H2N], sW3[H2N];
    __shared__ float sb3;
    __shared__ float sw1[H1N], szc[H1N];
    __shared__ float sbase[8 * H1N];
    __shared__ float redm[8][2], reds[8][2];

    int t = threadIdx.x;
    int g = t >> 6;
    int w = t & 63;
    int d = blockIdx.x * 8 + g;

    if (t < H1N * H2N) sW2[t] = prW2[t];
    if (t < H2N) { sb2[t] = prb2[t]; sW3[t] = prW3[t]; }
    if (t == 0) sb3 = prb3[0];
    if (t < H1N) { sw1[t] = prW1[t]; szc[t] = g_zc_pr[t]; }
    if (t < 8 * H1N) sbase[t] = g_yw_pr[blockIdx.x * 8 * H1N + t];
    __syncthreads();

    float limit = (float)(w + 1);
    const float* base = &sbase[g * H1N];
    float h2[H2N];
#pragma unroll
    for (int j2 = 0; j2 < H2N; j2++) h2[j2] = sb2[j2];
#pragma unroll
    for (int j = 0; j < H1N; j++) {
        float v = fmaxf(base[j] + szc[j] + limit * sw1[j], 0.f);
        const float4* w2 = (const float4*)&sW2[j * H2N];
#pragma unroll
        for (int q2 = 0; q2 < 4; q2++) {
            float4 wv = w2[q2];
            h2[4 * q2 + 0] += v * wv.x;
            h2[4 * q2 + 1] += v * wv.y;
            h2[4 * q2 + 2] += v * wv.z;
            h2[4 * q2 + 3] += v * wv.w;
        }
    }
    float logit = sb3;
#pragma unroll
    for (int j2 = 0; j2 < H2N; j2++) logit += fmaxf(h2[j2], 0.f) * sW3[j2];
    logit -= (1.f - msk[d * NW + w]) * 1000.f;

    float m = logit;
#pragma unroll
    for (int o = 16; o > 0; o >>= 1) m = fmaxf(m, __shfl_xor_sync(0xffffffffu, m, o));
    if ((w & 31) == 0) redm[g][w >> 5] = m;
    __syncthreads();
    m = fmaxf(redm[g][0], redm[g][1]);
    float e = expf(logit - m);
    float s = e;
#pragma unroll
    for (int o = 16; o > 0; o >>= 1) s += __shfl_xor_sync(0xffffffffu, s, o);
    if ((w & 31) == 0) reds[g][w >> 5] = s;
    __syncthreads();
    s = reds[g][0] + reds[g][1];
    out[nops + d * NW + w] = e / s;
}

// ---------------- K3: op MLP + fused global softmax -------------------------
// 128 thr, 256 rows/block. x staged via SMEM (coalesced LDG -> STS -> LDS.128)
// in 16-k chunks, register-prefetched. Consumption: 4 rows x 16 cols / thread.
// Dyn smem: sBuf 8448 floats (weights -> h1 stage) + sX 256*XPAD floats.
__global__ void __launch_bounds__(128, 3) k_ops(
    const float* __restrict__ x, const float* __restrict__ opW1,
    const float* __restrict__ opW2, const float* __restrict__ opb2,
    const float* __restrict__ opW3, const float* __restrict__ opb3,
    const float* __restrict__ op_msk, const int* __restrict__ num_ops,
    float* __restrict__ out, int nrows)
{
    extern __shared__ float dynS[];
    float* sBuf = dynS;                       // 8448 floats (weights / h1)
    float* sX   = dynS + 8448;                // 256*XPAD floats

    __shared__ int sCum[ND];
    __shared__ __align__(16) float sW2[H1N * H2N];
    __shared__ float sb2[H2N], sW3[H2N], szc[H1N];
    __shared__ float sb3;
    __shared__ float wred[4];
    __shared__ int wsum[4];
    __shared__ float sBcast;

    int t = threadIdx.x;
    int w = t >> 5, l = t & 31;
    int row0 = blockIdx.x * 256;

    // --- stage W1 x-part [k][32] + small weights ---
    {
        const float4* gW4 = (const float4*)opW1;
        float4* sW4 = (float4*)sBuf;
#pragma unroll
        for (int i = 0; i < 16; i++) sW4[i * 128 + t] = gW4[i * 128 + t];
    }
    for (int i = t; i < H1N * H2N; i += 128) sW2[i] = opW2[i];
    if (t < H2N) { sb2[t] = opb2[t]; sW3[t] = opW3[t]; }
    if (t < H1N) szc[t] = g_zc_op[t];
    if (t == 0) sb3 = opb3[0];

    // --- inline inclusive scan of num_ops into sCum ---
    {
        int vloc[8]; int tsum = 0;
#pragma unroll
        for (int i = 0; i < 8; i++) { vloc[i] = num_ops[t * 8 + i]; tsum += vloc[i]; }
        int sc = tsum;
#pragma unroll
        for (int o = 1; o < 32; o <<= 1) {
            int nv = __shfl_up_sync(0xffffffffu, sc, o);
            if (l >= o) sc += nv;
        }
        if (l == 31) wsum[w] = sc;
        __syncthreads();
        int woff = 0;
#pragma unroll
        for (int q = 0; q < 4; q++) if (q < w) woff += wsum[q];
        int run = woff + sc - tsum;
#pragma unroll
        for (int i = 0; i < 8; i++) { run += vloc[i]; sCum[t * 8 + i] = run; }
    }

    // --- main GEMM: 16 chunks of 16 k; coalesced staging ---
    int colhalf = t >> 6;               // 0: cols 0-15, 1: cols 16-31
    int rt = t & 63;

    // staging map for this thread: 8 float4 per chunk
    int sr[8], sc4[8];
#pragma unroll
    for (int i = 0; i < 8; i++) {
        int idx = i * 128 + t;
        sr[i] = idx >> 2;               // row 0..255
        sc4[i] = idx & 3;               // float4 within 16-k chunk
    }

    ull a0[8], a1[8], a2[8], a3[8];
#pragma unroll
    for (int q = 0; q < 8; q++) { a0[q] = 0ull; a1[q] = 0ull; a2[q] = 0ull; a3[q] = 0ull; }
    const ulonglong2* sWu = (const ulonglong2*)sBuf;

    float4 pf[8];
#pragma unroll
    for (int i = 0; i < 8; i++) {
        int row = min(row0 + sr[i], nrows - 1);
        pf[i] = *(const float4*)&x[(size_t)row * E + sc4[i] * 4];
    }

    for (int ch = 0; ch < 16; ch++) {
        __syncthreads();                 // previous chunk fully consumed
#pragma unroll
        for (int i = 0; i < 8; i++)
            *(float4*)&sX[sr[i] * XPAD + sc4[i] * 4] = pf[i];
        if (ch < 15) {
#pragma unroll
            for (int i = 0; i < 8; i++) {
                int row = min(row0 + sr[i], nrows - 1);
                pf[i] = *(const float4*)&x[(size_t)row * E + (ch + 1) * 16 + sc4[i] * 4];
            }
        }
        __syncthreads();                 // chunk ch visible
#pragma unroll
        for (int k4 = 0; k4 < 4; k4++) {
            float4 v0 = *(const float4*)&sX[(rt      ) * XPAD + k4 * 4];
            float4 v1 = *(const float4*)&sX[(rt +  64) * XPAD + k4 * 4];
            float4 v2 = *(const float4*)&sX[(rt + 128) * XPAD + k4 * 4];
            float4 v3 = *(const float4*)&sX[(rt + 192) * XPAD + k4 * 4];
            float f0[4] = {v0.x, v0.y, v0.z, v0.w};
            float f1[4] = {v1.x, v1.y, v1.z, v1.w};
            float f2[4] = {v2.x, v2.y, v2.z, v2.w};
            float f3[4] = {v3.x, v3.y, v3.z, v3.w};
#pragma unroll
            for (int kk = 0; kk < 4; kk++) {
                int k = ch * 16 + k4 * 4 + kk;
                ull s0 = splat2(f0[kk]);
                ull s1 = splat2(f1[kk]);
                ull s2 = splat2(f2[kk]);
                ull s3 = splat2(f3[kk]);
                const ulonglong2* wp = &sWu[k * 8 + colhalf * 4];
                ulonglong2 w0 = wp[0], w1 = wp[1], w2 = wp[2], w3 = wp[3];
                a0[0] = fma2(s0, w0.x, a0[0]); a0[1] = fma2(s0, w0.y, a0[1]);
                a0[2] = fma2(s0, w1.x, a0[2]); a0[3] = fma2(s0, w1.y, a0[3]);
                a0[4] = fma2(s0, w2.x, a0[4]); a0[5] = fma2(s0, w2.y, a0[5]);
                a0[6] = fma2(s0, w3.x, a0[6]); a0[7] = fma2(s0, w3.y, a0[7]);
                a1[0] = fma2(s1, w0.x, a1[0]); a1[1] = fma2(s1, w0.y, a1[1]);
                a1[2] = fma2(s1, w1.x, a1[2]); a1[3] = fma2(s1, w1.y, a1[3]);
                a1[4] = fma2(s1, w2.x, a1[4]); a1[5] = fma2(s1, w2.y, a1[5]);
                a1[6] = fma2(s1, w3.x, a1[6]); a1[7] = fma2(s1, w3.y, a1[7]);
                a2[0] = fma2(s2, w0.x, a2[0]); a2[1] = fma2(s2, w0.y, a2[1]);
                a2[2] = fma2(s2, w1.x, a2[2]); a2[3] = fma2(s2, w1.y, a2[3]);
                a2[4] = fma2(s2, w2.x, a2[4]); a2[5] = fma2(s2, w2.y, a2[5]);
                a2[6] = fma2(s2, w3.x, a2[6]); a2[7] = fma2(s2, w3.y, a2[7]);
                a3[0] = fma2(s3, w0.x, a3[0]); a3[1] = fma2(s3, w0.y, a3[1]);
                a3[2] = fma2(s3, w1.x, a3[2]); a3[3] = fma2(s3, w1.y, a3[3]);
                a3[4] = fma2(s3, w2.x, a3[4]); a3[5] = fma2(s3, w2.y, a3[5]);
                a3[6] = fma2(s3, w3.x, a3[6]); a3[7] = fma2(s3, w3.y, a3[7]);
            }
        }
    }

    // --- stage h1 to sBuf (stride-33), reuse weight region ---
    __syncthreads();
    {
        float* d0 = &sBuf[(rt      ) * 33 + colhalf * 16];
        float* d1 = &sBuf[(rt +  64) * 33 + colhalf * 16];
        float* d2 = &sBuf[(rt + 128) * 33 + colhalf * 16];
        float* d3 = &sBuf[(rt + 192) * 33 + colhalf * 16];
#pragma unroll
        for (int q = 0; q < 8; q++) {
            unpack2(a0[q], d0[2 * q], d0[2 * q + 1]);
            unpack2(a1[q], d1[2 * q], d1[2 * q + 1]);
            unpack2(a2[q], d2[2 * q], d2[2 * q + 1]);
            unpack2(a3[q], d3[2 * q], d3[2 * q + 1]);
        }
    }
    __syncthreads();

    // --- epilogue: 2 rows per thread, logits stay in registers ---
    float lg[2];
    float m = -3.402823466e38f;
#pragma unroll
    for (int r = 0; r < 2; r++) {
        int lr = t + r * 128;
        int i = row0 + lr;
        lg[r] = -3.402823466e38f;
        if (i < nrows) {
            int d = 0;
#pragma unroll
            for (int s = 512; s > 0; s >>= 1)
                if (d + s <= ND - 1 && sCum[d + s - 1] <= i) d += s;
            const float* hs = &sBuf[lr * 33];
            const float* bw = &g_yw_op[d * H1N];
            float h2[H2N];
#pragma unroll
            for (int j2 = 0; j2 < H2N; j2++) h2[j2] = sb2[j2];
#pragma unroll
            for (int j = 0; j < H1N; j++) {
                float v = fmaxf(hs[j] + bw[j] + szc[j], 0.f);
                const float4* w2 = (const float4*)&sW2[j * H2N];
#pragma unroll
                for (int q2 = 0; q2 < 4; q2++) {
                    float4 wv = w2[q2];
                    h2[4 * q2 + 0] += v * wv.x;
                    h2[4 * q2 + 1] += v * wv.y;
                    h2[4 * q2 + 2] += v * wv.z;
                    h2[4 * q2 + 3] += v * wv.w;
                }
            }
            float logit = sb3;
#pragma unroll
            for (int j2 = 0; j2 < H2N; j2++) logit += fmaxf(h2[j2], 0.f) * sW3[j2];
            logit -= (1.f - op_msk[i]) * 1000.f;
            lg[r] = logit;
            m = fmaxf(m, logit);
        }
    }

#pragma unroll
    for (int o = 16; o > 0; o >>= 1) m = fmaxf(m, __shfl_xor_sync(0xffffffffu, m, o));
    if (l == 0) wred[w] = m;
    __syncthreads();

    // --- grid barrier 1: global max ---
    if (t == 0) {
        float bm = fmaxf(fmaxf(wred[0], wred[1]), fmaxf(wred[2], wred[3]));
        atomicMax(&g_maxbits, encf(bm));
        __threadfence();
        atomicAdd(&g_cnt1, 1u);
        volatile unsigned* vc = &g_cnt1;
        while (*vc < gridDim.x) { }
        __threadfence();
        sBcast = decf(*(volatile unsigned*)&g_maxbits);
    }
    __syncthreads();
    float gm = sBcast;

    float e0 = (lg[0] > -1e38f) ? expf(lg[0] - gm) : 0.f;
    float e1 = (lg[1] > -1e38f) ? expf(lg[1] - gm) : 0.f;
    float s = e0 + e1;
#pragma unroll
    for (int o = 16; o > 0; o >>= 1) s += __shfl_xor_sync(0xffffffffu, s, o);
    if (l == 0) wred[w] = s;
    __syncthreads();

    // --- grid barrier 2: global sum ---
    if (t == 0) {
        float bs = wred[0] + wred[1] + wred[2] + wred[3];
        atomicAdd(&g_sum, bs);
        __threadfence();
        atomicAdd(&g_cnt2, 1u);
        volatile unsigned* vc = &g_cnt2;
        while (*vc < gridDim.x) { }
        __threadfence();
        sBcast = 1.f / *(volatile float*)&g_sum;
    }
    __syncthreads();
    float inv = sBcast;

    int i0 = row0 + t, i1 = row0 + t + 128;
    if (i0 < nrows) out[i0] = e0 * inv;
    if (i1 < nrows) out[i1] = e1 * inv;
}

// ---------------- launcher ----------------
extern "C" void kernel_launch(void* const* d_in, const int* in_sizes, int n_in,
                              void* d_out, int out_size) {
    int o = (n_in >= 20) ? 2 : 0;
    const int*   num_ops = (const int*)d_in[0];
    const float* x       = (const float*)d_in[1 + o];
    const float* y       = (const float*)d_in[2 + o];
    const float* z       = (const float*)d_in[3 + o];
    const float* op_msk  = (const float*)d_in[4 + o];
    const float* pr_msk  = (const float*)d_in[5 + o];
    const float* opW1    = (const float*)d_in[6 + o];
    const float* opb1    = (const float*)d_in[7 + o];
    const float* opW2    = (const float*)d_in[8 + o];
    const float* opb2    = (const float*)d_in[9 + o];
    const float* opW3    = (const float*)d_in[10 + o];
    const float* opb3    = (const float*)d_in[11 + o];
    const float* prW1    = (const float*)d_in[12 + o];
    const float* prb1    = (const float*)d_in[13 + o];
    const float* prW2    = (const float*)d_in[14 + o];
    const float* prb2    = (const float*)d_in[15 + o];
    const float* prW3    = (const float*)d_in[16 + o];
    const float* prb3    = (const float*)d_in[17 + o];
    float* out = (float*)d_out;

    int n = in_sizes[1 + o] / E;   // total ops (102400)

    static int smem_set = 0;
    int dyn = (8448 + 256 * XPAD) * (int)sizeof(float);   // 54272 B
    if (!smem_set) {
        cudaFuncSetAttribute(k_ops, cudaFuncAttributeMaxDynamicSharedMemorySize, dyn);
        smem_set = 1;
    }

    k_pre<<<130, 128>>>(opW1, opb1, prW1, prb1, z, y);
    k_prlvl<<<ND / 8, 512>>>(prW1, prW2, prb2, prW3, prb3, pr_msk, out, n);
    k_ops<<<(n + 255) / 256, 128, dyn>>>(x, opW1, opW2, opb2, opW3, opb3,
                                         op_msk, num_ops, out, n);
}